// round 6
// baseline (speedup 1.0000x reference)
#include <cuda_runtime.h>
#include <cuda_bf16.h>
#include <math.h>

#define NUSER 50000
#define NITEM 100000
#define NNODE 150000
#define DD    64
#define NNZV  2400000
#define BB    1024
#define NSLOT 3072   // 1024 users + 1024 pos + 1024 neg

// ---------------- device scratch (statically allocated; no cudaMalloc) ----------
__device__ float4 g_E4[NNODE * 16];    // node embeddings, updated per layer (38.4MB)
__device__ float4 g_LE4[NNODE * 16];   // SpMM accumulator L@E (38.4MB)
__device__ float  g_mlp[BB * DD];      // user MLP output
__device__ int    g_slot[NSLOT];       // output slot -> node id
__device__ unsigned char g_flag[NNODE];// node needed in final layer?

// ---------------- f32x2 packed-math helpers --------------------------------------
__device__ __forceinline__ unsigned long long pack2(float x, float y) {
    unsigned long long r;
    asm("mov.b64 %0, {%1, %2};" : "=l"(r) : "f"(x), "f"(y));
    return r;
}
__device__ __forceinline__ void unpack2(unsigned long long v, float &x, float &y) {
    asm("mov.b64 {%0, %1}, %2;" : "=f"(x), "=f"(y) : "l"(v));
}
__device__ __forceinline__ unsigned long long ffma2(unsigned long long a,
                                                    unsigned long long b,
                                                    unsigned long long c) {
    unsigned long long d;
    asm("fma.rn.f32x2 %0, %1, %2, %3;" : "=l"(d) : "l"(a), "l"(b), "l"(c));
    return d;
}

// ---------------- init: E = concat(user_emb, item_emb) ---------------------------
__global__ void k_copyE(const float4 *__restrict__ ue, const float4 *__restrict__ ie) {
    int i = blockIdx.x * blockDim.x + threadIdx.x;
    if (i >= NNODE * 16) return;
    g_E4[i] = (i < NUSER * 16) ? ue[i] : ie[i - NUSER * 16];
}

// ---------------- user MLP: (feat @ W1 + b1) @ W2 + b2 ---------------------------
__global__ void k_mlp(const float *__restrict__ feat,
                      const float *__restrict__ w1, const float *__restrict__ b1,
                      const float *__restrict__ w2, const float *__restrict__ b2) {
    int b = blockIdx.x * blockDim.x + threadIdx.x;
    if (b >= BB) return;
    float f0 = feat[b * 4 + 0], f1 = feat[b * 4 + 1];
    float f2 = feat[b * 4 + 2], f3 = feat[b * 4 + 3];
    float h[32];
#pragma unroll
    for (int j = 0; j < 32; j++)
        h[j] = b1[j] + f0 * w1[j] + f1 * w1[32 + j] + f2 * w1[64 + j] + f3 * w1[96 + j];
#pragma unroll 4
    for (int o = 0; o < 64; o++) {
        float a = b2[o];
#pragma unroll
        for (int j = 0; j < 32; j++) a += h[j] * w2[j * 64 + o];
        g_mlp[b * 64 + o] = a;
    }
}

// ---------------- scatter update with last-occurrence-wins -----------------------
__global__ void k_update(const int *__restrict__ uidx,
                         const float *__restrict__ uemb,
                         const float *__restrict__ ratio) {
    int b = blockIdx.x * blockDim.x + threadIdx.x;
    if (b >= BB) return;
    int u = uidx[b];
    for (int b2 = b + 1; b2 < BB; b2++)
        if (uidx[b2] == u) return;          // a later write to this row wins
    float r = *ratio;
    float *erow = (float *)(g_E4 + u * 16);
#pragma unroll
    for (int j = 0; j < 64; j++)
        erow[j] = uemb[u * 64 + j] * (1.0f - r) + g_mlp[b * 64 + j] * r;
}

// ---------------- output-slot node map + needed-node flags -----------------------
__global__ void k_zeroflag() {
    int i = blockIdx.x * blockDim.x + threadIdx.x;
    if (i < NNODE) g_flag[i] = 0;
}
__global__ void k_slots(const int *__restrict__ ui, const int *__restrict__ pi,
                        const int *__restrict__ ni) {
    int s = blockIdx.x * blockDim.x + threadIdx.x;
    if (s >= NSLOT) return;
    int node;
    if (s < 1024)       node = ui[s];
    else if (s < 2048)  node = NUSER + pi[s - 1024];
    else                node = NUSER + ni[s - 2048];
    g_slot[s] = node;
    g_flag[node] = 1;
}

// ---------------- zero the SpMM accumulator --------------------------------------
__global__ void k_zeroLE() {
    int i = blockIdx.x * blockDim.x + threadIdx.x;
    if (i < NNODE * 16) g_LE4[i] = make_float4(0.f, 0.f, 0.f, 0.f);
}

// ---------------- COO SpMM via float4 global reductions --------------------------
// 16 threads per nnz, one float4 each. Coalesced gather of E[col] rows.
template <bool FLAGGED>
__global__ void k_spmm(const int *__restrict__ row, const int *__restrict__ col,
                       const float *__restrict__ val) {
    long long gid = (long long)blockIdx.x * blockDim.x + threadIdx.x;
    int i = (int)(gid >> 4);
    int j = (int)(gid & 15);
    if (i >= NNZV) return;
    int r = __ldg(row + i);
    if (FLAGGED && !g_flag[r]) return;
    int c = __ldg(col + i);
    float v = __ldg(val + i);
    float4 x = g_E4[c * 16 + j];
    atomicAdd(&g_LE4[r * 16 + j], make_float4(v * x.x, v * x.y, v * x.z, v * x.w));
}

// ---------------- full-layer GEMM + leaky_relu, E updated in place ---------------
// msg = (LE+E) @ W1 + (LE*E) @ W2 + (b1+b2);  E = leaky_relu(msg)
__global__ __launch_bounds__(128) void k_gemm(const float *__restrict__ w1,
                                              const float *__restrict__ b1,
                                              const float *__restrict__ w2,
                                              const float *__restrict__ b2) {
    __shared__ unsigned long long sW1[2048], sW2[2048], sB[32];
    const unsigned long long *w1p = (const unsigned long long *)w1;
    const unsigned long long *w2p = (const unsigned long long *)w2;
    for (int i = threadIdx.x; i < 2048; i += 128) { sW1[i] = w1p[i]; sW2[i] = w2p[i]; }
    if (threadIdx.x < 32) {
        int t = threadIdx.x;
        sB[t] = pack2(b1[2 * t] + b2[2 * t], b1[2 * t + 1] + b2[2 * t + 1]);
    }
    __syncthreads();

    int rrow = blockIdx.x * 128 + threadIdx.x;
    if (rrow >= NNODE) return;

    unsigned long long acc[32];
#pragma unroll
    for (int j = 0; j < 32; j++) acc[j] = sB[j];

    const float *lep = (const float *)(g_LE4 + rrow * 16);
    const float *ep  = (const float *)(g_E4 + rrow * 16);

#pragma unroll 4
    for (int k = 0; k < 64; k++) {
        float le = lep[k], e = ep[k];
        float a = le + e, m = le * e;
        unsigned long long a2 = pack2(a, a), m2 = pack2(m, m);
        const ulonglong2 *wA = (const ulonglong2 *)(sW1 + k * 32);
        const ulonglong2 *wB = (const ulonglong2 *)(sW2 + k * 32);
#pragma unroll
        for (int j = 0; j < 16; j++) {
            ulonglong2 pa = wA[j];
            ulonglong2 pb = wB[j];
            acc[2 * j]     = ffma2(a2, pa.x, acc[2 * j]);
            acc[2 * j + 1] = ffma2(a2, pa.y, acc[2 * j + 1]);
            acc[2 * j]     = ffma2(m2, pb.x, acc[2 * j]);
            acc[2 * j + 1] = ffma2(m2, pb.y, acc[2 * j + 1]);
        }
    }

    float4 *out = g_E4 + rrow * 16;
#pragma unroll
    for (int j = 0; j < 16; j++) {
        float x0, x1, x2, x3;
        unpack2(acc[2 * j], x0, x1);
        unpack2(acc[2 * j + 1], x2, x3);
        x0 = (x0 >= 0.f) ? x0 : 0.2f * x0;
        x1 = (x1 >= 0.f) ? x1 : 0.2f * x1;
        x2 = (x2 >= 0.f) ? x2 : 0.2f * x2;
        x3 = (x3 >= 0.f) ? x3 : 0.2f * x3;
        out[j] = make_float4(x0, x1, x2, x3);
    }
}

// ---------------- gather slot rows into d_out (optionally L2-normalized) ---------
__global__ void k_gather(float *__restrict__ out, int col_off, int do_norm) {
    int t = blockIdx.x * blockDim.x + threadIdx.x;
    int slot = t >> 5, lane = t & 31;
    if (slot >= NSLOT) return;
    int node = g_slot[slot];
    const float2 *rowp = (const float2 *)(g_E4 + node * 16);
    float2 v = rowp[lane];
    if (do_norm) {
        float s = v.x * v.x + v.y * v.y;
#pragma unroll
        for (int o = 16; o > 0; o >>= 1) s += __shfl_xor_sync(0xffffffffu, s, o);
        float sc = 1.0f / fmaxf(sqrtf(s), 1e-12f);
        v.x *= sc; v.y *= sc;
    }
    ((float2 *)(out + (size_t)slot * 256 + col_off))[lane] = v;
}

// ---------------- layer 3: GEMM + leaky + norm for the 3072 needed rows only -----
__global__ __launch_bounds__(128) void k_layer3(const float *__restrict__ w1,
                                                const float *__restrict__ b1,
                                                const float *__restrict__ w2,
                                                const float *__restrict__ b2,
                                                float *__restrict__ out) {
    __shared__ unsigned long long sW1[2048], sW2[2048], sB[32];
    const unsigned long long *w1p = (const unsigned long long *)w1;
    const unsigned long long *w2p = (const unsigned long long *)w2;
    for (int i = threadIdx.x; i < 2048; i += 128) { sW1[i] = w1p[i]; sW2[i] = w2p[i]; }
    if (threadIdx.x < 32) {
        int t = threadIdx.x;
        sB[t] = pack2(b1[2 * t] + b2[2 * t], b1[2 * t + 1] + b2[2 * t + 1]);
    }
    __syncthreads();

    int s = blockIdx.x * 128 + threadIdx.x;
    if (s >= NSLOT) return;
    int rrow = g_slot[s];

    unsigned long long acc[32];
#pragma unroll
    for (int j = 0; j < 32; j++) acc[j] = sB[j];

    const float *lep = (const float *)(g_LE4 + rrow * 16);
    const float *ep  = (const float *)(g_E4 + rrow * 16);

#pragma unroll 4
    for (int k = 0; k < 64; k++) {
        float le = lep[k], e = ep[k];
        float a = le + e, m = le * e;
        unsigned long long a2 = pack2(a, a), m2 = pack2(m, m);
        const ulonglong2 *wA = (const ulonglong2 *)(sW1 + k * 32);
        const ulonglong2 *wB = (const ulonglong2 *)(sW2 + k * 32);
#pragma unroll
        for (int j = 0; j < 16; j++) {
            ulonglong2 pa = wA[j];
            ulonglong2 pb = wB[j];
            acc[2 * j]     = ffma2(a2, pa.x, acc[2 * j]);
            acc[2 * j + 1] = ffma2(a2, pa.y, acc[2 * j + 1]);
            acc[2 * j]     = ffma2(m2, pb.x, acc[2 * j]);
            acc[2 * j + 1] = ffma2(m2, pb.y, acc[2 * j + 1]);
        }
    }

    // leaky_relu, then L2 norm, write straight to output cols [192,256)
    float ss = 0.f;
#pragma unroll
    for (int j = 0; j < 32; j++) {
        float x, y;
        unpack2(acc[j], x, y);
        x = (x >= 0.f) ? x : 0.2f * x;
        y = (y >= 0.f) ? y : 0.2f * y;
        acc[j] = pack2(x, y);
        ss += x * x + y * y;
    }
    float sc = 1.0f / fmaxf(sqrtf(ss), 1e-12f);
    float *op = out + (size_t)s * 256 + 192;
#pragma unroll
    for (int j = 0; j < 16; j++) {
        float x0, x1, x2, x3;
        unpack2(acc[2 * j], x0, x1);
        unpack2(acc[2 * j + 1], x2, x3);
        ((float4 *)op)[j] = make_float4(x0 * sc, x1 * sc, x2 * sc, x3 * sc);
    }
}

// =================================================================================
extern "C" void kernel_launch(void* const* d_in, const int* in_sizes, int n_in,
                              void* d_out, int out_size) {
    const float *user_emb, *item_emb, *user_feat, *lin1_w, *lin1_b, *lin2_w, *lin2_b;
    const float *w1, *b1, *w2, *b2, *lap_val, *mlp_ratio;
    const int *lap_row, *lap_col, *user_idx, *pos_idx, *neg_idx;

    if (in_sizes[2] == 4096) {
        // reference-signature order
        user_emb  = (const float *)d_in[0];
        item_emb  = (const float *)d_in[1];
        user_feat = (const float *)d_in[2];
        lin1_w    = (const float *)d_in[3];
        lin1_b    = (const float *)d_in[4];
        lin2_w    = (const float *)d_in[5];
        lin2_b    = (const float *)d_in[6];
        w1        = (const float *)d_in[7];
        b1        = (const float *)d_in[8];
        w2        = (const float *)d_in[9];
        b2        = (const float *)d_in[10];
        lap_val   = (const float *)d_in[11];
        mlp_ratio = (const float *)d_in[12];
        lap_row   = (const int *)d_in[13];
        lap_col   = (const int *)d_in[14];
        user_idx  = (const int *)d_in[15];
        pos_idx   = (const int *)d_in[16];
        neg_idx   = (const int *)d_in[17];
    } else {
        // setup_inputs dict order
        user_emb  = (const float *)d_in[0];
        item_emb  = (const float *)d_in[1];
        lin1_w    = (const float *)d_in[2];
        lin1_b    = (const float *)d_in[3];
        lin2_w    = (const float *)d_in[4];
        lin2_b    = (const float *)d_in[5];
        w1        = (const float *)d_in[6];
        b1        = (const float *)d_in[7];
        w2        = (const float *)d_in[8];
        b2        = (const float *)d_in[9];
        lap_row   = (const int *)d_in[10];
        lap_col   = (const int *)d_in[11];
        lap_val   = (const float *)d_in[12];
        user_idx  = (const int *)d_in[13];
        user_feat = (const float *)d_in[14];
        pos_idx   = (const int *)d_in[15];
        neg_idx   = (const int *)d_in[16];
        mlp_ratio = (const float *)d_in[17];
    }

    float *out = (float *)d_out;

    const int T = 256;
    int gE   = (NNODE * 16 + T - 1) / T;     // 9375
    int gFlag = (NNODE + T - 1) / T;
    int gSlot = (NSLOT + T - 1) / T;
    int gGath = (NSLOT * 32 + T - 1) / T;    // 384
    long long spmm_threads = (long long)NNZV * 16;
    int gSpmm = (int)((spmm_threads + T - 1) / T);  // 150000
    int gGemm = (NNODE + 127) / 128;         // 1172
    int gL3   = (NSLOT + 127) / 128;         // 24

    // ---- build E0 ----
    k_copyE<<<gE, T>>>((const float4 *)user_emb, (const float4 *)item_emb);
    k_mlp<<<(BB + T - 1) / T, T>>>(user_feat, lin1_w, lin1_b, lin2_w, lin2_b);
    k_update<<<(BB + T - 1) / T, T>>>(user_idx, user_emb, mlp_ratio);

    // ---- output slot map + needed flags ----
    k_zeroflag<<<gFlag, T>>>();
    k_slots<<<gSlot, T>>>(user_idx, pos_idx, neg_idx);

    // ---- all_E[:, 0:64] = E0 (un-normalized) ----
    k_gather<<<gGath, T>>>(out, 0, 0);

    // ---- layers 1 and 2 (full graph) ----
    for (int l = 0; l < 2; l++) {
        k_zeroLE<<<gE, T>>>();
        k_spmm<false><<<gSpmm, T>>>(lap_row, lap_col, lap_val);
        k_gemm<<<gGemm, 128>>>(w1 + l * 4096, b1 + l * 64, w2 + l * 4096, b2 + l * 64);
        k_gather<<<gGath, T>>>(out, 64 * (l + 1), 1);
    }

    // ---- layer 3: only the 3072 output rows matter ----
    k_zeroLE<<<gE, T>>>();
    k_spmm<true><<<gSpmm, T>>>(lap_row, lap_col, lap_val);
    k_layer3<<<gL3, 128>>>(w1 + 2 * 4096, b1 + 2 * 64, w2 + 2 * 4096, b2 + 2 * 64, out);
}

// round 9
// speedup vs baseline: 1.5278x; 1.5278x over previous
#include <cuda_runtime.h>
#include <cuda_bf16.h>
#include <math.h>

#define NUSER 50000
#define NITEM 100000
#define NNODE 150000
#define DD    64
#define NNZV  2400000
#define BB    1024
#define NSLOT 3072          // 1024 users + 1024 pos + 1024 neg
#define SCAN_TILE 1024
#define NTILES ((NNODE + SCAN_TILE - 1) / SCAN_TILE)   // 147

// ---------------- device scratch (statically allocated; no cudaMalloc) ----------
__device__ float4 g_E4[NNODE * 16];      // node embeddings (38.4MB)
__device__ float4 g_LE4[NNODE * 16];     // SpMM result L@E (38.4MB)
__device__ float  g_mlp[BB * DD];
__device__ int    g_slot[NSLOT];
__device__ unsigned char g_flag3[NNODE]; // node is an output slot (layer-3 row)
__device__ unsigned char g_flag2[NNODE]; // node needed after layer 2
// CSR build
__device__ int  g_cnt[NNODE];
__device__ int  g_rp[NNODE + 1];
__device__ int  g_pos[NNODE];
__device__ int  g_tilesum[NTILES + 1];
__device__ int2 g_cv[NNZV];              // (col, val bits) row-sorted (19.2MB)

// ---------------- f32x2 packed-math helpers --------------------------------------
__device__ __forceinline__ unsigned long long pack2(float x, float y) {
    unsigned long long r;
    asm("mov.b64 %0, {%1, %2};" : "=l"(r) : "f"(x), "f"(y));
    return r;
}
__device__ __forceinline__ void unpack2(unsigned long long v, float &x, float &y) {
    asm("mov.b64 {%0, %1}, %2;" : "=f"(x), "=f"(y) : "l"(v));
}
__device__ __forceinline__ unsigned long long ffma2(unsigned long long a,
                                                    unsigned long long b,
                                                    unsigned long long c) {
    unsigned long long d;
    asm("fma.rn.f32x2 %0, %1, %2, %3;" : "=l"(d) : "l"(a), "l"(b), "l"(c));
    return d;
}

// ---------------- init: E = concat(user_emb, item_emb) ---------------------------
__global__ void k_copyE(const float4 *__restrict__ ue, const float4 *__restrict__ ie) {
    int i = blockIdx.x * blockDim.x + threadIdx.x;
    if (i >= NNODE * 16) return;
    g_E4[i] = (i < NUSER * 16) ? ue[i] : ie[i - NUSER * 16];
}

// ---------------- user MLP -------------------------------------------------------
__global__ void k_mlp(const float *__restrict__ feat,
                      const float *__restrict__ w1, const float *__restrict__ b1,
                      const float *__restrict__ w2, const float *__restrict__ b2) {
    int b = blockIdx.x * blockDim.x + threadIdx.x;
    if (b >= BB) return;
    float f0 = feat[b * 4 + 0], f1 = feat[b * 4 + 1];
    float f2 = feat[b * 4 + 2], f3 = feat[b * 4 + 3];
    float h[32];
#pragma unroll
    for (int j = 0; j < 32; j++)
        h[j] = b1[j] + f0 * w1[j] + f1 * w1[32 + j] + f2 * w1[64 + j] + f3 * w1[96 + j];
#pragma unroll 4
    for (int o = 0; o < 64; o++) {
        float a = b2[o];
#pragma unroll
        for (int j = 0; j < 32; j++) a += h[j] * w2[j * 64 + o];
        g_mlp[b * 64 + o] = a;
    }
}

// ---------------- scatter update, last-occurrence-wins ---------------------------
__global__ void k_update(const int *__restrict__ uidx,
                         const float *__restrict__ uemb,
                         const float *__restrict__ ratio) {
    int b = blockIdx.x * blockDim.x + threadIdx.x;
    if (b >= BB) return;
    int u = uidx[b];
    for (int b2 = b + 1; b2 < BB; b2++)
        if (uidx[b2] == u) return;
    float r = *ratio;
    float *erow = (float *)(g_E4 + u * 16);
#pragma unroll
    for (int j = 0; j < 64; j++)
        erow[j] = uemb[u * 64 + j] * (1.0f - r) + g_mlp[b * 64 + j] * r;
}

// ---------------- zero aux arrays ------------------------------------------------
__global__ void k_zero_aux() {
    int i = blockIdx.x * blockDim.x + threadIdx.x;
    if (i < NNODE) { g_cnt[i] = 0; g_flag3[i] = 0; g_flag2[i] = 0; }
}

// ---------------- slot map + flags -----------------------------------------------
__global__ void k_slots(const int *__restrict__ ui, const int *__restrict__ pi,
                        const int *__restrict__ ni) {
    int s = blockIdx.x * blockDim.x + threadIdx.x;
    if (s >= NSLOT) return;
    int node;
    if (s < 1024)       node = ui[s];
    else if (s < 2048)  node = NUSER + pi[s - 1024];
    else                node = NUSER + ni[s - 2048];
    g_slot[s] = node;
    g_flag3[node] = 1;
    g_flag2[node] = 1;
}

// flag2 |= cols of nnz whose row is a slot
__global__ void k_flag2(const int *__restrict__ row, const int *__restrict__ col) {
    int i = blockIdx.x * blockDim.x + threadIdx.x;
    if (i >= NNZV) return;
    if (g_flag3[row[i]]) g_flag2[col[i]] = 1;
}

// ---------------- CSR build ------------------------------------------------------
__global__ void k_hist(const int *__restrict__ row) {
    int i = blockIdx.x * blockDim.x + threadIdx.x;
    if (i < NNZV) atomicAdd(&g_cnt[row[i]], 1);
}

// 256-thread block, SCAN_TILE elems/block: tile-local exclusive scan
__global__ void k_scan1() {
    __shared__ int wsum[8];
    int tid = threadIdx.x, lane = tid & 31, wid = tid >> 5;
    int idx = blockIdx.x * SCAN_TILE + tid * 4;
    int v0 = (idx + 0 < NNODE) ? g_cnt[idx + 0] : 0;
    int v1 = (idx + 1 < NNODE) ? g_cnt[idx + 1] : 0;
    int v2 = (idx + 2 < NNODE) ? g_cnt[idx + 2] : 0;
    int v3 = (idx + 3 < NNODE) ? g_cnt[idx + 3] : 0;
    int s = v0 + v1 + v2 + v3;
    int x = s;
#pragma unroll
    for (int o = 1; o < 32; o <<= 1) {
        int y = __shfl_up_sync(0xffffffffu, x, o);
        if (lane >= o) x += y;
    }
    if (lane == 31) wsum[wid] = x;
    __syncthreads();
    if (wid == 0) {
        int y = (lane < 8) ? wsum[lane] : 0;
#pragma unroll
        for (int o = 1; o < 8; o <<= 1) {
            int z = __shfl_up_sync(0xffffffffu, y, o);
            if (lane >= o) y += z;
        }
        if (lane < 8) wsum[lane] = y;
    }
    __syncthreads();
    int run = x - s + (wid > 0 ? wsum[wid - 1] : 0);
    if (idx + 0 < NNODE) g_rp[idx + 0] = run; run += v0;
    if (idx + 1 < NNODE) g_rp[idx + 1] = run; run += v1;
    if (idx + 2 < NNODE) g_rp[idx + 2] = run; run += v2;
    if (idx + 3 < NNODE) g_rp[idx + 3] = run;
    if (tid == 0) g_tilesum[blockIdx.x] = wsum[7];
}

// single block: exclusive scan of tile sums
__global__ void k_scan2() {
    __shared__ int wsum[8];
    int tid = threadIdx.x, lane = tid & 31, wid = tid >> 5;
    int v = (tid < NTILES) ? g_tilesum[tid] : 0;
    int x = v;
#pragma unroll
    for (int o = 1; o < 32; o <<= 1) {
        int y = __shfl_up_sync(0xffffffffu, x, o);
        if (lane >= o) x += y;
    }
    if (lane == 31) wsum[wid] = x;
    __syncthreads();
    if (wid == 0) {
        int y = (lane < 8) ? wsum[lane] : 0;
#pragma unroll
        for (int o = 1; o < 8; o <<= 1) {
            int z = __shfl_up_sync(0xffffffffu, y, o);
            if (lane >= o) y += z;
        }
        if (lane < 8) wsum[lane] = y;
    }
    __syncthreads();
    int excl = x - v + (wid > 0 ? wsum[wid - 1] : 0);
    if (tid < NTILES) g_tilesum[tid] = excl;
}

__global__ void k_scan3() {
    int i = blockIdx.x * blockDim.x + threadIdx.x;
    if (i < NNODE) {
        int v = g_rp[i] + g_tilesum[i >> 10];
        g_rp[i] = v;
        g_pos[i] = v;
    }
    if (i == NNODE) g_rp[NNODE] = NNZV;
}

__global__ void k_scatter(const int *__restrict__ row, const int *__restrict__ col,
                          const float *__restrict__ val) {
    int i = blockIdx.x * blockDim.x + threadIdx.x;
    if (i >= NNZV) return;
    int p = atomicAdd(&g_pos[row[i]], 1);
    g_cv[p] = make_int2(col[i], __float_as_int(val[i]));
}

// ---------------- CSR SpMM: one warp per row, no atomics -------------------------
// MODE 0 = all rows, 1 = flag2 rows only, 2 = slot list
template <int MODE>
__global__ void k_spmm_csr() {
    int w = (blockIdx.x * blockDim.x + threadIdx.x) >> 5;
    int lane = threadIdx.x & 31;
    int r;
    if (MODE == 2) {
        if (w >= NSLOT) return;
        r = g_slot[w];
    } else {
        if (w >= NNODE) return;
        r = w;
        if (MODE == 1 && !g_flag2[r]) return;
    }
    int j = g_rp[r], end = g_rp[r + 1];
    const float2 *E2 = (const float2 *)g_E4;
    float ax = 0.f, ay = 0.f;
    for (; j + 4 <= end; j += 4) {
        int2 c0 = __ldg(g_cv + j + 0);
        int2 c1 = __ldg(g_cv + j + 1);
        int2 c2 = __ldg(g_cv + j + 2);
        int2 c3 = __ldg(g_cv + j + 3);
        float2 e0 = E2[c0.x * 32 + lane];
        float2 e1 = E2[c1.x * 32 + lane];
        float2 e2 = E2[c2.x * 32 + lane];
        float2 e3 = E2[c3.x * 32 + lane];
        ax += __int_as_float(c0.y) * e0.x; ay += __int_as_float(c0.y) * e0.y;
        ax += __int_as_float(c1.y) * e1.x; ay += __int_as_float(c1.y) * e1.y;
        ax += __int_as_float(c2.y) * e2.x; ay += __int_as_float(c2.y) * e2.y;
        ax += __int_as_float(c3.y) * e3.x; ay += __int_as_float(c3.y) * e3.y;
    }
    for (; j < end; j++) {
        int2 c = __ldg(g_cv + j);
        float2 e = E2[c.x * 32 + lane];
        ax += __int_as_float(c.y) * e.x;
        ay += __int_as_float(c.y) * e.y;
    }
    ((float2 *)g_LE4)[r * 32 + lane] = make_float2(ax, ay);
}

// ---------------- full-layer GEMM + leaky_relu, E in place -----------------------
template <int MODE>   // 0 = all rows, 1 = flag2 only
__global__ __launch_bounds__(128) void k_gemm(const float *__restrict__ w1,
                                              const float *__restrict__ b1,
                                              const float *__restrict__ w2,
                                              const float *__restrict__ b2) {
    __shared__ unsigned long long sW1[2048], sW2[2048], sB[32];
    const unsigned long long *w1p = (const unsigned long long *)w1;
    const unsigned long long *w2p = (const unsigned long long *)w2;
    for (int i = threadIdx.x; i < 2048; i += 128) { sW1[i] = w1p[i]; sW2[i] = w2p[i]; }
    if (threadIdx.x < 32) {
        int t = threadIdx.x;
        sB[t] = pack2(b1[2 * t] + b2[2 * t], b1[2 * t + 1] + b2[2 * t + 1]);
    }
    __syncthreads();

    int rrow = blockIdx.x * 128 + threadIdx.x;
    if (rrow >= NNODE) return;
    if (MODE == 1 && !g_flag2[rrow]) return;

    unsigned long long acc[32];
#pragma unroll
    for (int j = 0; j < 32; j++) acc[j] = sB[j];

    const float *lep = (const float *)(g_LE4 + rrow * 16);
    const float *ep  = (const float *)(g_E4 + rrow * 16);

#pragma unroll 4
    for (int k = 0; k < 64; k++) {
        float le = lep[k], e = ep[k];
        float a = le + e, m = le * e;
        unsigned long long a2 = pack2(a, a), m2 = pack2(m, m);
        const ulonglong2 *wA = (const ulonglong2 *)(sW1 + k * 32);
        const ulonglong2 *wB = (const ulonglong2 *)(sW2 + k * 32);
#pragma unroll
        for (int j = 0; j < 16; j++) {
            ulonglong2 pa = wA[j];
            ulonglong2 pb = wB[j];
            acc[2 * j]     = ffma2(a2, pa.x, acc[2 * j]);
            acc[2 * j + 1] = ffma2(a2, pa.y, acc[2 * j + 1]);
            acc[2 * j]     = ffma2(m2, pb.x, acc[2 * j]);
            acc[2 * j + 1] = ffma2(m2, pb.y, acc[2 * j + 1]);
        }
    }

    float4 *out = g_E4 + rrow * 16;
#pragma unroll
    for (int j = 0; j < 16; j++) {
        float x0, x1, x2, x3;
        unpack2(acc[2 * j], x0, x1);
        unpack2(acc[2 * j + 1], x2, x3);
        x0 = (x0 >= 0.f) ? x0 : 0.2f * x0;
        x1 = (x1 >= 0.f) ? x1 : 0.2f * x1;
        x2 = (x2 >= 0.f) ? x2 : 0.2f * x2;
        x3 = (x3 >= 0.f) ? x3 : 0.2f * x3;
        out[j] = make_float4(x0, x1, x2, x3);
    }
}

// ---------------- gather slot rows into d_out ------------------------------------
__global__ void k_gather(float *__restrict__ out, int col_off, int do_norm) {
    int t = blockIdx.x * blockDim.x + threadIdx.x;
    int slot = t >> 5, lane = t & 31;
    if (slot >= NSLOT) return;
    int node = g_slot[slot];
    const float2 *rowp = (const float2 *)(g_E4 + node * 16);
    float2 v = rowp[lane];
    if (do_norm) {
        float s = v.x * v.x + v.y * v.y;
#pragma unroll
        for (int o = 16; o > 0; o >>= 1) s += __shfl_xor_sync(0xffffffffu, s, o);
        float sc = 1.0f / fmaxf(sqrtf(s), 1e-12f);
        v.x *= sc; v.y *= sc;
    }
    ((float2 *)(out + (size_t)slot * 256 + col_off))[lane] = v;
}

// ---------------- layer 3: GEMM + leaky + norm for slot rows only ----------------
__global__ __launch_bounds__(128) void k_layer3(const float *__restrict__ w1,
                                                const float *__restrict__ b1,
                                                const float *__restrict__ w2,
                                                const float *__restrict__ b2,
                                                float *__restrict__ out) {
    __shared__ unsigned long long sW1[2048], sW2[2048], sB[32];
    const unsigned long long *w1p = (const unsigned long long *)w1;
    const unsigned long long *w2p = (const unsigned long long *)w2;
    for (int i = threadIdx.x; i < 2048; i += 128) { sW1[i] = w1p[i]; sW2[i] = w2p[i]; }
    if (threadIdx.x < 32) {
        int t = threadIdx.x;
        sB[t] = pack2(b1[2 * t] + b2[2 * t], b1[2 * t + 1] + b2[2 * t + 1]);
    }
    __syncthreads();

    int s = blockIdx.x * 128 + threadIdx.x;
    if (s >= NSLOT) return;
    int rrow = g_slot[s];

    unsigned long long acc[32];
#pragma unroll
    for (int j = 0; j < 32; j++) acc[j] = sB[j];

    const float *lep = (const float *)(g_LE4 + rrow * 16);
    const float *ep  = (const float *)(g_E4 + rrow * 16);

#pragma unroll 4
    for (int k = 0; k < 64; k++) {
        float le = lep[k], e = ep[k];
        float a = le + e, m = le * e;
        unsigned long long a2 = pack2(a, a), m2 = pack2(m, m);
        const ulonglong2 *wA = (const ulonglong2 *)(sW1 + k * 32);
        const ulonglong2 *wB = (const ulonglong2 *)(sW2 + k * 32);
#pragma unroll
        for (int j = 0; j < 16; j++) {
            ulonglong2 pa = wA[j];
            ulonglong2 pb = wB[j];
            acc[2 * j]     = ffma2(a2, pa.x, acc[2 * j]);
            acc[2 * j + 1] = ffma2(a2, pa.y, acc[2 * j + 1]);
            acc[2 * j]     = ffma2(m2, pb.x, acc[2 * j]);
            acc[2 * j + 1] = ffma2(m2, pb.y, acc[2 * j + 1]);
        }
    }

    float ss = 0.f;
#pragma unroll
    for (int j = 0; j < 32; j++) {
        float x, y;
        unpack2(acc[j], x, y);
        x = (x >= 0.f) ? x : 0.2f * x;
        y = (y >= 0.f) ? y : 0.2f * y;
        acc[j] = pack2(x, y);
        ss += x * x + y * y;
    }
    float sc = 1.0f / fmaxf(sqrtf(ss), 1e-12f);
    float *op = out + (size_t)s * 256 + 192;
#pragma unroll
    for (int j = 0; j < 16; j++) {
        float x0, x1, x2, x3;
        unpack2(acc[2 * j], x0, x1);
        unpack2(acc[2 * j + 1], x2, x3);
        ((float4 *)op)[j] = make_float4(x0 * sc, x1 * sc, x2 * sc, x3 * sc);
    }
}

// =================================================================================
extern "C" void kernel_launch(void* const* d_in, const int* in_sizes, int n_in,
                              void* d_out, int out_size) {
    const float *user_emb, *item_emb, *user_feat, *lin1_w, *lin1_b, *lin2_w, *lin2_b;
    const float *w1, *b1, *w2, *b2, *lap_val, *mlp_ratio;
    const int *lap_row, *lap_col, *user_idx, *pos_idx, *neg_idx;

    if (in_sizes[2] == 4096) {
        user_emb  = (const float *)d_in[0];
        item_emb  = (const float *)d_in[1];
        user_feat = (const float *)d_in[2];
        lin1_w    = (const float *)d_in[3];
        lin1_b    = (const float *)d_in[4];
        lin2_w    = (const float *)d_in[5];
        lin2_b    = (const float *)d_in[6];
        w1        = (const float *)d_in[7];
        b1        = (const float *)d_in[8];
        w2        = (const float *)d_in[9];
        b2        = (const float *)d_in[10];
        lap_val   = (const float *)d_in[11];
        mlp_ratio = (const float *)d_in[12];
        lap_row   = (const int *)d_in[13];
        lap_col   = (const int *)d_in[14];
        user_idx  = (const int *)d_in[15];
        pos_idx   = (const int *)d_in[16];
        neg_idx   = (const int *)d_in[17];
    } else {
        user_emb  = (const float *)d_in[0];
        item_emb  = (const float *)d_in[1];
        lin1_w    = (const float *)d_in[2];
        lin1_b    = (const float *)d_in[3];
        lin2_w    = (const float *)d_in[4];
        lin2_b    = (const float *)d_in[5];
        w1        = (const float *)d_in[6];
        b1        = (const float *)d_in[7];
        w2        = (const float *)d_in[8];
        b2        = (const float *)d_in[9];
        lap_row   = (const int *)d_in[10];
        lap_col   = (const int *)d_in[11];
        lap_val   = (const float *)d_in[12];
        user_idx  = (const int *)d_in[13];
        user_feat = (const float *)d_in[14];
        pos_idx   = (const int *)d_in[15];
        neg_idx   = (const int *)d_in[16];
        mlp_ratio = (const float *)d_in[17];
    }

    float *out = (float *)d_out;

    const int T = 256;
    int gE     = (NNODE * 16 + T - 1) / T;
    int gNode  = (NNODE + T - 1) / T;
    int gNode1 = (NNODE + 1 + T - 1) / T;
    int gSlot  = (NSLOT + T - 1) / T;
    int gGath  = (NSLOT * 32 + T - 1) / T;
    int gNnz   = (NNZV + T - 1) / T;
    int gSpmm  = (NNODE * 32 + T - 1) / T;    // warp per row
    int gSpmmS = (NSLOT * 32 + T - 1) / T;
    int gGemm  = (NNODE + 127) / 128;
    int gL3    = (NSLOT + 127) / 128;

    // ---- E0 + flags ----
    k_copyE<<<gE, T>>>((const float4 *)user_emb, (const float4 *)item_emb);
    k_mlp<<<(BB + T - 1) / T, T>>>(user_feat, lin1_w, lin1_b, lin2_w, lin2_b);
    k_update<<<(BB + T - 1) / T, T>>>(user_idx, user_emb, mlp_ratio);
    k_zero_aux<<<gNode, T>>>();
    k_slots<<<gSlot, T>>>(user_idx, pos_idx, neg_idx);
    k_flag2<<<gNnz, T>>>(lap_row, lap_col);

    // ---- CSR build ----
    k_hist<<<gNnz, T>>>(lap_row);
    k_scan1<<<NTILES, 256>>>();
    k_scan2<<<1, 256>>>();
    k_scan3<<<gNode1, T>>>();
    k_scatter<<<gNnz, T>>>(lap_row, lap_col, lap_val);

    // ---- all_E[:, 0:64] = E0 ----
    k_gather<<<gGath, T>>>(out, 0, 0);

    // ---- layer 1 (full) ----
    k_spmm_csr<0><<<gSpmm, T>>>();
    k_gemm<0><<<gGemm, 128>>>(w1, b1, w2, b2);
    k_gather<<<gGath, T>>>(out, 64, 1);

    // ---- layer 2 (flag2 rows only) ----
    k_spmm_csr<1><<<gSpmm, T>>>();
    k_gemm<1><<<gGemm, 128>>>(w1 + 4096, b1 + 64, w2 + 4096, b2 + 64);
    k_gather<<<gGath, T>>>(out, 128, 1);

    // ---- layer 3 (slot rows only) ----
    k_spmm_csr<2><<<gSpmmS, T>>>();
    k_layer3<<<gL3, 128>>>(w1 + 2 * 4096, b1 + 2 * 64, w2 + 2 * 4096, b2 + 2 * 64, out);
}

// round 10
// speedup vs baseline: 1.5471x; 1.0126x over previous
#include <cuda_runtime.h>
#include <cuda_bf16.h>
#include <math.h>

#define NUSER 50000
#define NITEM 100000
#define NNODE 150000
#define DD    64
#define NNZV  2400000
#define BB    1024
#define NSLOT 3072          // 1024 users + 1024 pos + 1024 neg
#define SCAN_TILE 1024
#define NTILES ((NNODE + SCAN_TILE - 1) / SCAN_TILE)   // 147

// ---------------- device scratch (statically allocated; no cudaMalloc) ----------
__device__ float4 g_E4[NNODE * 16];      // node embeddings (38.4MB)
__device__ float4 g_LE4[NNODE * 16];     // SpMM result L@E (38.4MB)
__device__ float  g_mlp[BB * DD];
__device__ int    g_slot[NSLOT];
__device__ unsigned char g_flag3[NNODE]; // node is an output slot (layer-3 row)
__device__ unsigned char g_flag2[NNODE]; // node needed after layer 2
__device__ int  g_list2[NNODE];          // dense list of flag2 rows
__device__ int  g_n2;                    // count of flag2 rows
// CSR build
__device__ int  g_cnt[NNODE];
__device__ int  g_rp[NNODE + 1];
__device__ int  g_pos[NNODE];
__device__ int  g_tilesum[NTILES + 1];
__device__ int2 g_cv[NNZV];              // (col, val bits) row-sorted (19.2MB)

// ---------------- f32x2 packed-math helpers --------------------------------------
__device__ __forceinline__ unsigned long long pack2(float x, float y) {
    unsigned long long r;
    asm("mov.b64 %0, {%1, %2};" : "=l"(r) : "f"(x), "f"(y));
    return r;
}
__device__ __forceinline__ void unpack2(unsigned long long v, float &x, float &y) {
    asm("mov.b64 {%0, %1}, %2;" : "=f"(x), "=f"(y) : "l"(v));
}
__device__ __forceinline__ unsigned long long ffma2(unsigned long long a,
                                                    unsigned long long b,
                                                    unsigned long long c) {
    unsigned long long d;
    asm("fma.rn.f32x2 %0, %1, %2, %3;" : "=l"(d) : "l"(a), "l"(b), "l"(c));
    return d;
}

// E0 row pointer: user rows live in g_E4 (copied+updated), item rows read from input
__device__ __forceinline__ const float2 *e0row(int c, const float2 *__restrict__ item2) {
    return (c < NUSER) ? ((const float2 *)g_E4) + (size_t)c * 32
                       : item2 + (size_t)(c - NUSER) * 32;
}

// ================= launch 1: copy user-E + zero aux + user MLP ===================
// blocks [0,3125): copy user rows; [3125,3711): zero aux; [3711,3715): MLP
#define INIT_COPY_BLKS 3125
#define INIT_ZERO_BLKS 586
#define INIT_BLKS (INIT_COPY_BLKS + INIT_ZERO_BLKS + 4)
__global__ void k_init(const float4 *__restrict__ ue,
                       const float *__restrict__ feat,
                       const float *__restrict__ w1, const float *__restrict__ b1,
                       const float *__restrict__ w2, const float *__restrict__ b2) {
    int bid = blockIdx.x, tid = threadIdx.x;
    if (bid < INIT_COPY_BLKS) {
        int i = bid * 256 + tid;
        if (i < NUSER * 16) g_E4[i] = ue[i];
        return;
    }
    bid -= INIT_COPY_BLKS;
    if (bid < INIT_ZERO_BLKS) {
        int i = bid * 256 + tid;
        if (i < NNODE) { g_cnt[i] = 0; g_flag3[i] = 0; g_flag2[i] = 0; }
        if (i == 0) g_n2 = 0;
        return;
    }
    bid -= INIT_ZERO_BLKS;
    int b = bid * 256 + tid;
    if (b >= BB) return;
    float f0 = feat[b * 4 + 0], f1 = feat[b * 4 + 1];
    float f2 = feat[b * 4 + 2], f3 = feat[b * 4 + 3];
    float h[32];
#pragma unroll
    for (int j = 0; j < 32; j++)
        h[j] = b1[j] + f0 * w1[j] + f1 * w1[32 + j] + f2 * w1[64 + j] + f3 * w1[96 + j];
#pragma unroll 4
    for (int o = 0; o < 64; o++) {
        float a = b2[o];
#pragma unroll
        for (int j = 0; j < 32; j++) a += h[j] * w2[j * 64 + o];
        g_mlp[b * 64 + o] = a;
    }
}

// ================= launch 2: scatter-update (last wins) + slots/flags ============
__global__ void k_prep(const int *__restrict__ uidx, const float *__restrict__ uemb,
                       const float *__restrict__ ratio,
                       const int *__restrict__ pi, const int *__restrict__ ni) {
    int bid = blockIdx.x, tid = threadIdx.x;
    if (bid < 4) {
        int b = bid * 256 + tid;
        if (b >= BB) return;
        int u = uidx[b];
        for (int b2 = b + 1; b2 < BB; b2++)
            if (uidx[b2] == u) return;       // later write wins
        float r = *ratio;
        float *erow = (float *)(g_E4 + u * 16);
#pragma unroll
        for (int j = 0; j < 64; j++)
            erow[j] = uemb[u * 64 + j] * (1.0f - r) + g_mlp[b * 64 + j] * r;
        return;
    }
    int s = (bid - 4) * 256 + tid;
    if (s >= NSLOT) return;
    int node;
    if (s < 1024)       node = uidx[s];
    else if (s < 2048)  node = NUSER + pi[s - 1024];
    else                node = NUSER + ni[s - 2048];
    g_slot[s] = node;
    g_flag3[node] = 1;
    g_flag2[node] = 1;
}

// ---------------- shared gather body --------------------------------------------
__device__ __forceinline__ void gather_body(int t, float *__restrict__ out, int col_off,
                                            int do_norm, const float2 *__restrict__ item2,
                                            int src0) {
    int slot = t >> 5, lane = t & 31;
    if (slot >= NSLOT) return;
    int node = g_slot[slot];
    const float2 *rowp = src0 ? e0row(node, item2)
                              : ((const float2 *)g_E4) + (size_t)node * 32;
    float2 v = rowp[lane];
    if (do_norm) {
        float s = v.x * v.x + v.y * v.y;
#pragma unroll
        for (int o = 16; o > 0; o >>= 1) s += __shfl_xor_sync(0xffffffffu, s, o);
        float sc = 1.0f / fmaxf(sqrtf(s), 1e-12f);
        v.x *= sc; v.y *= sc;
    }
    ((float2 *)(out + (size_t)slot * 256 + col_off))[lane] = v;
}

// ================= launch 3: histogram + flag2 propagate + gather0 ===============
#define NNZ_BLKS 9375
__global__ void k_nnzpass(const int *__restrict__ row, const int *__restrict__ col,
                          float *__restrict__ out, const float2 *__restrict__ item2) {
    int bid = blockIdx.x, tid = threadIdx.x;
    if (bid < NNZ_BLKS) {
        int i = bid * 256 + tid;
        if (i >= NNZV) return;
        int r = __ldg(row + i);
        atomicAdd(&g_cnt[r], 1);
        if (g_flag3[r]) g_flag2[__ldg(col + i)] = 1;
        return;
    }
    gather_body((bid - NNZ_BLKS) * 256 + tid, out, 0, 0, item2, 1);
}

// ================= launch 4: tile-local exclusive scan ===========================
__global__ void k_scan1() {
    __shared__ int wsum[8];
    int tid = threadIdx.x, lane = tid & 31, wid = tid >> 5;
    int idx = blockIdx.x * SCAN_TILE + tid * 4;
    int v0 = (idx + 0 < NNODE) ? g_cnt[idx + 0] : 0;
    int v1 = (idx + 1 < NNODE) ? g_cnt[idx + 1] : 0;
    int v2 = (idx + 2 < NNODE) ? g_cnt[idx + 2] : 0;
    int v3 = (idx + 3 < NNODE) ? g_cnt[idx + 3] : 0;
    int s = v0 + v1 + v2 + v3;
    int x = s;
#pragma unroll
    for (int o = 1; o < 32; o <<= 1) {
        int y = __shfl_up_sync(0xffffffffu, x, o);
        if (lane >= o) x += y;
    }
    if (lane == 31) wsum[wid] = x;
    __syncthreads();
    if (wid == 0) {
        int y = (lane < 8) ? wsum[lane] : 0;
#pragma unroll
        for (int o = 1; o < 8; o <<= 1) {
            int z = __shfl_up_sync(0xffffffffu, y, o);
            if (lane >= o) y += z;
        }
        if (lane < 8) wsum[lane] = y;
    }
    __syncthreads();
    int run = x - s + (wid > 0 ? wsum[wid - 1] : 0);
    if (idx + 0 < NNODE) g_rp[idx + 0] = run; run += v0;
    if (idx + 1 < NNODE) g_rp[idx + 1] = run; run += v1;
    if (idx + 2 < NNODE) g_rp[idx + 2] = run; run += v2;
    if (idx + 3 < NNODE) g_rp[idx + 3] = run;
    if (tid == 0) g_tilesum[blockIdx.x] = wsum[7];
}

// ================= launch 5: finalize row_ptr + build flag2 list =================
// block b covers nodes [b*256,(b+1)*256); whole block is inside one scan tile.
__global__ void k_scan23() {
    __shared__ int ws[8];
    int tid = threadIdx.x, lane = tid & 31, wid = tid >> 5;
    int tile = blockIdx.x >> 2;
    int v = (tid < tile) ? g_tilesum[tid] : 0;   // tile <= 146 < 256
#pragma unroll
    for (int o = 16; o > 0; o >>= 1) v += __shfl_xor_sync(0xffffffffu, v, o);
    if (lane == 0) ws[wid] = v;
    __syncthreads();
    if (tid == 0) {
        int s = 0;
#pragma unroll
        for (int i = 0; i < 8; i++) s += ws[i];
        ws[0] = s;
    }
    __syncthreads();
    int S = ws[0];
    int i = blockIdx.x * 256 + tid;
    if (i < NNODE) {
        int val = g_rp[i] + S;
        g_rp[i] = val;
        g_pos[i] = val;
        if (g_flag2[i]) {
            int p = atomicAdd(&g_n2, 1);
            g_list2[p] = i;
        }
    }
    if (blockIdx.x == 0 && tid == 0) g_rp[NNODE] = NNZV;
}

// ================= launch 6: scatter (col,val) row-sorted ========================
__global__ void k_scatter(const int *__restrict__ row, const int *__restrict__ col,
                          const float *__restrict__ val) {
    int i = blockIdx.x * blockDim.x + threadIdx.x;
    if (i >= NNZV) return;
    int p = atomicAdd(&g_pos[row[i]], 1);
    g_cv[p] = make_int2(col[i], __float_as_int(val[i]));
}

// ================= CSR SpMM: one warp per row, no atomics ========================
// MODE 0 = all rows reading E0 (select user/item), 1 = list2 rows, 2 = slot rows
template <int MODE>
__global__ void k_spmm(const float2 *__restrict__ item2, int gather_base,
                       float *__restrict__ out, int col_off) {
    int bid = blockIdx.x;
    if (gather_base >= 0 && bid >= gather_base) {
        gather_body((bid - gather_base) * 256 + threadIdx.x, out, col_off, 1, item2, 0);
        return;
    }
    int w = (bid * blockDim.x + threadIdx.x) >> 5;
    int lane = threadIdx.x & 31;
    int r;
    if (MODE == 0)      { if (w >= NNODE) return; r = w; }
    else if (MODE == 1) { if (w >= g_n2)  return; r = g_list2[w]; }
    else                { if (w >= NSLOT) return; r = g_slot[w]; }
    int j = __ldg(&g_rp[r]), end = __ldg(&g_rp[r + 1]);
    const float2 *E2 = (const float2 *)g_E4;
    float ax = 0.f, ay = 0.f;

#define LDE(c) (MODE == 0 ? __ldg(e0row((c), item2) + lane) \
                          : __ldg(E2 + (size_t)(c) * 32 + lane))
    if ((j & 1) && j < end) {
        int2 c = __ldg(g_cv + j);
        float2 e = LDE(c.x);
        float v = __int_as_float(c.y);
        ax += v * e.x; ay += v * e.y;
        j++;
    }
    for (; j + 8 <= end; j += 8) {
        int4 q0 = __ldg((const int4 *)(g_cv + j));
        int4 q1 = __ldg((const int4 *)(g_cv + j + 2));
        int4 q2 = __ldg((const int4 *)(g_cv + j + 4));
        int4 q3 = __ldg((const int4 *)(g_cv + j + 6));
        float2 e0 = LDE(q0.x), e1 = LDE(q0.z);
        float2 e2 = LDE(q1.x), e3 = LDE(q1.z);
        float2 e4 = LDE(q2.x), e5 = LDE(q2.z);
        float2 e6 = LDE(q3.x), e7 = LDE(q3.z);
        ax += __int_as_float(q0.y) * e0.x; ay += __int_as_float(q0.y) * e0.y;
        ax += __int_as_float(q0.w) * e1.x; ay += __int_as_float(q0.w) * e1.y;
        ax += __int_as_float(q1.y) * e2.x; ay += __int_as_float(q1.y) * e2.y;
        ax += __int_as_float(q1.w) * e3.x; ay += __int_as_float(q1.w) * e3.y;
        ax += __int_as_float(q2.y) * e4.x; ay += __int_as_float(q2.y) * e4.y;
        ax += __int_as_float(q2.w) * e5.x; ay += __int_as_float(q2.w) * e5.y;
        ax += __int_as_float(q3.y) * e6.x; ay += __int_as_float(q3.y) * e6.y;
        ax += __int_as_float(q3.w) * e7.x; ay += __int_as_float(q3.w) * e7.y;
    }
    for (; j < end; j++) {
        int2 c = __ldg(g_cv + j);
        float2 e = LDE(c.x);
        float v = __int_as_float(c.y);
        ax += v * e.x; ay += v * e.y;
    }
#undef LDE
    ((float2 *)g_LE4)[(size_t)r * 32 + lane] = make_float2(ax, ay);
}

// ================= full-layer GEMM + leaky_relu, E in place ======================
// MODE 0 = all rows (layer 1, E0 via select), 1 = list2 rows (layer 2)
template <int MODE>
__global__ __launch_bounds__(128) void k_gemm(const float *__restrict__ w1,
                                              const float *__restrict__ b1,
                                              const float *__restrict__ w2,
                                              const float *__restrict__ b2,
                                              const float2 *__restrict__ item2) {
    if (MODE == 1 && (int)blockIdx.x * 128 >= g_n2) return;
    __shared__ unsigned long long sW1[2048], sW2[2048], sB[32];
    const unsigned long long *w1p = (const unsigned long long *)w1;
    const unsigned long long *w2p = (const unsigned long long *)w2;
    for (int i = threadIdx.x; i < 2048; i += 128) { sW1[i] = w1p[i]; sW2[i] = w2p[i]; }
    if (threadIdx.x < 32) {
        int t = threadIdx.x;
        sB[t] = pack2(b1[2 * t] + b2[2 * t], b1[2 * t + 1] + b2[2 * t + 1]);
    }
    __syncthreads();

    int idx = blockIdx.x * 128 + threadIdx.x;
    int rrow;
    if (MODE == 0) { if (idx >= NNODE) return; rrow = idx; }
    else           { if (idx >= g_n2)  return; rrow = g_list2[idx]; }

    unsigned long long acc[32];
#pragma unroll
    for (int j = 0; j < 32; j++) acc[j] = sB[j];

    const float *lep = (const float *)(g_LE4 + (size_t)rrow * 16);
    const float *ep  = (MODE == 0) ? (const float *)e0row(rrow, item2)
                                   : (const float *)(g_E4 + (size_t)rrow * 16);

#pragma unroll 4
    for (int k = 0; k < 64; k++) {
        float le = lep[k], e = ep[k];
        float a = le + e, m = le * e;
        unsigned long long a2 = pack2(a, a), m2 = pack2(m, m);
        const ulonglong2 *wA = (const ulonglong2 *)(sW1 + k * 32);
        const ulonglong2 *wB = (const ulonglong2 *)(sW2 + k * 32);
#pragma unroll
        for (int j = 0; j < 16; j++) {
            ulonglong2 pa = wA[j];
            ulonglong2 pb = wB[j];
            acc[2 * j]     = ffma2(a2, pa.x, acc[2 * j]);
            acc[2 * j + 1] = ffma2(a2, pa.y, acc[2 * j + 1]);
            acc[2 * j]     = ffma2(m2, pb.x, acc[2 * j]);
            acc[2 * j + 1] = ffma2(m2, pb.y, acc[2 * j + 1]);
        }
    }

    float4 *o = g_E4 + (size_t)rrow * 16;
#pragma unroll
    for (int j = 0; j < 16; j++) {
        float x0, x1, x2, x3;
        unpack2(acc[2 * j], x0, x1);
        unpack2(acc[2 * j + 1], x2, x3);
        x0 = (x0 >= 0.f) ? x0 : 0.2f * x0;
        x1 = (x1 >= 0.f) ? x1 : 0.2f * x1;
        x2 = (x2 >= 0.f) ? x2 : 0.2f * x2;
        x3 = (x3 >= 0.f) ? x3 : 0.2f * x3;
        o[j] = make_float4(x0, x1, x2, x3);
    }
}

// ================= final layer: GEMM + leaky + norm for slot rows ================
__global__ __launch_bounds__(128) void k_layer3(const float *__restrict__ w1,
                                                const float *__restrict__ b1,
                                                const float *__restrict__ w2,
                                                const float *__restrict__ b2,
                                                float *__restrict__ out) {
    __shared__ unsigned long long sW1[2048], sW2[2048], sB[32];
    const unsigned long long *w1p = (const unsigned long long *)w1;
    const unsigned long long *w2p = (const unsigned long long *)w2;
    for (int i = threadIdx.x; i < 2048; i += 128) { sW1[i] = w1p[i]; sW2[i] = w2p[i]; }
    if (threadIdx.x < 32) {
        int t = threadIdx.x;
        sB[t] = pack2(b1[2 * t] + b2[2 * t], b1[2 * t + 1] + b2[2 * t + 1]);
    }
    __syncthreads();

    int s = blockIdx.x * 128 + threadIdx.x;
    if (s >= NSLOT) return;
    int rrow = g_slot[s];

    unsigned long long acc[32];
#pragma unroll
    for (int j = 0; j < 32; j++) acc[j] = sB[j];

    const float *lep = (const float *)(g_LE4 + (size_t)rrow * 16);
    const float *ep  = (const float *)(g_E4 + (size_t)rrow * 16);

#pragma unroll 4
    for (int k = 0; k < 64; k++) {
        float le = lep[k], e = ep[k];
        float a = le + e, m = le * e;
        unsigned long long a2 = pack2(a, a), m2 = pack2(m, m);
        const ulonglong2 *wA = (const ulonglong2 *)(sW1 + k * 32);
        const ulonglong2 *wB = (const ulonglong2 *)(sW2 + k * 32);
#pragma unroll
        for (int j = 0; j < 16; j++) {
            ulonglong2 pa = wA[j];
            ulonglong2 pb = wB[j];
            acc[2 * j]     = ffma2(a2, pa.x, acc[2 * j]);
            acc[2 * j + 1] = ffma2(a2, pa.y, acc[2 * j + 1]);
            acc[2 * j]     = ffma2(m2, pb.x, acc[2 * j]);
            acc[2 * j + 1] = ffma2(m2, pb.y, acc[2 * j + 1]);
        }
    }

    float ss = 0.f;
#pragma unroll
    for (int j = 0; j < 32; j++) {
        float x, y;
        unpack2(acc[j], x, y);
        x = (x >= 0.f) ? x : 0.2f * x;
        y = (y >= 0.f) ? y : 0.2f * y;
        acc[j] = pack2(x, y);
        ss += x * x + y * y;
    }
    float sc = 1.0f / fmaxf(sqrtf(ss), 1e-12f);
    float *op = out + (size_t)s * 256 + 192;
#pragma unroll
    for (int j = 0; j < 16; j++) {
        float x0, x1, x2, x3;
        unpack2(acc[2 * j], x0, x1);
        unpack2(acc[2 * j + 1], x2, x3);
        ((float4 *)op)[j] = make_float4(x0 * sc, x1 * sc, x2 * sc, x3 * sc);
    }
}

// =================================================================================
extern "C" void kernel_launch(void* const* d_in, const int* in_sizes, int n_in,
                              void* d_out, int out_size) {
    const float *user_emb, *item_emb, *user_feat, *lin1_w, *lin1_b, *lin2_w, *lin2_b;
    const float *w1, *b1, *w2, *b2, *lap_val, *mlp_ratio;
    const int *lap_row, *lap_col, *user_idx, *pos_idx, *neg_idx;

    if (in_sizes[2] == 4096) {
        user_emb  = (const float *)d_in[0];
        item_emb  = (const float *)d_in[1];
        user_feat = (const float *)d_in[2];
        lin1_w    = (const float *)d_in[3];
        lin1_b    = (const float *)d_in[4];
        lin2_w    = (const float *)d_in[5];
        lin2_b    = (const float *)d_in[6];
        w1        = (const float *)d_in[7];
        b1        = (const float *)d_in[8];
        w2        = (const float *)d_in[9];
        b2        = (const float *)d_in[10];
        lap_val   = (const float *)d_in[11];
        mlp_ratio = (const float *)d_in[12];
        lap_row   = (const int *)d_in[13];
        lap_col   = (const int *)d_in[14];
        user_idx  = (const int *)d_in[15];
        pos_idx   = (const int *)d_in[16];
        neg_idx   = (const int *)d_in[17];
    } else {
        user_emb  = (const float *)d_in[0];
        item_emb  = (const float *)d_in[1];
        lin1_w    = (const float *)d_in[2];
        lin1_b    = (const float *)d_in[3];
        lin2_w    = (const float *)d_in[4];
        lin2_b    = (const float *)d_in[5];
        w1        = (const float *)d_in[6];
        b1        = (const float *)d_in[7];
        w2        = (const float *)d_in[8];
        b2        = (const float *)d_in[9];
        lap_row   = (const int *)d_in[10];
        lap_col   = (const int *)d_in[11];
        lap_val   = (const float *)d_in[12];
        user_idx  = (const int *)d_in[13];
        user_feat = (const float *)d_in[14];
        pos_idx   = (const int *)d_in[15];
        neg_idx   = (const int *)d_in[16];
        mlp_ratio = (const float *)d_in[17];
    }

    float *out = (float *)d_out;
    const float2 *item2 = (const float2 *)item_emb;

    const int T = 256;
    const int gGath  = (NSLOT * 32 + T - 1) / T;    // 384 gather blocks
    const int gNnz   = (NNZV + T - 1) / T;          // 9375
    const int gSpmmF = (NNODE * 32 + T - 1) / T;    // 18750 (warp per row)
    const int gSpmmS = (NSLOT * 32 + T - 1) / T;    // 384
    const int gGemm  = (NNODE + 127) / 128;         // 1172
    const int gL3    = (NSLOT + 127) / 128;         // 24

    // 1: copy user E0 + zero aux + user MLP
    k_init<<<INIT_BLKS, T>>>((const float4 *)user_emb, user_feat,
                             lin1_w, lin1_b, lin2_w, lin2_b);
    // 2: scatter-update users + slot map/flags
    k_prep<<<16, T>>>(user_idx, user_emb, mlp_ratio, pos_idx, neg_idx);
    // 3: row histogram + flag2 propagate + gather E0 slots -> out[:,0:64]
    k_nnzpass<<<NNZ_BLKS + gGath, T>>>(lap_row, lap_col, out, item2);
    // 4-5: scan
    k_scan1<<<NTILES, T>>>();
    k_scan23<<<(NNODE + T - 1) / T, T>>>();
    // 6: CSR scatter
    k_scatter<<<gNnz, T>>>(lap_row, lap_col, lap_val);

    // 7: layer-1 SpMM (full, E0 select)
    k_spmm<0><<<gSpmmF, T>>>(item2, -1, nullptr, 0);
    // 8: layer-1 GEMM (full)
    k_gemm<0><<<gGemm, 128>>>(w1, b1, w2, b2, item2);
    // 9: layer-2 SpMM (list2 rows) || gather E1 slots -> out[:,64:128]
    k_spmm<1><<<gSpmmF + gGath, T>>>(item2, gSpmmF, out, 64);
    // 10: layer-2 GEMM (list2 rows)
    k_gemm<1><<<gGemm, 128>>>(w1 + 4096, b1 + 64, w2 + 4096, b2 + 64, item2);
    // 11: layer-3 SpMM (slot rows) || gather E2 slots -> out[:,128:192]
    k_spmm<2><<<gSpmmS + gGath, T>>>(item2, gSpmmS, out, 128);
    // 12: layer-3 GEMM + leaky + norm -> out[:,192:256]
    k_layer3<<<gL3, 128>>>(w1 + 2 * 4096, b1 + 2 * 64, w2 + 2 * 4096, b2 + 2 * 64, out);
}

// round 13
// speedup vs baseline: 1.6079x; 1.0393x over previous
#include <cuda_runtime.h>
#include <cuda_bf16.h>
#include <cuda_fp16.h>
#include <math.h>

#define NUSER 50000
#define NITEM 100000
#define NNODE 150000
#define DD    64
#define NNZV  2400000
#define BB    1024
#define NSLOT 3072
#define SCAN_TILE 1024
#define NTILES ((NNODE + SCAN_TILE - 1) / SCAN_TILE)   // 147
#define SP2_WARPS 37888                                 // 4736 blocks * 8 warps

// ---------------- device scratch --------------------------------------------------
__device__ float4  g_E4[NNODE * 16];     // fp32 node embeddings (38.4MB)
__device__ __half2 g_Eh[NNODE * 32];     // fp16 mirror for SpMM gather (19.2MB)
__device__ float4  g_LE4[NNODE * 16];    // SpMM result (38.4MB)
__device__ int     g_slot[NSLOT];
__device__ unsigned char g_flag3[NNODE];
__device__ unsigned char g_flag2[NNODE];
__device__ int  g_list2[NNODE];
__device__ int  g_n2;
__device__ int  g_cnt[NNODE];
__device__ int  g_rp[NNODE + 1];
__device__ int  g_pos[NNODE];
__device__ int  g_tflag[NTILES];         // lookback: 0=not ready, else total+1
__device__ int2 g_cv[NNZV];              // (col, val bits) row-sorted (19.2MB)

// ---------------- f32x2 packed-math helpers ---------------------------------------
__device__ __forceinline__ unsigned long long pack2(float x, float y) {
    unsigned long long r;
    asm("mov.b64 %0, {%1, %2};" : "=l"(r) : "f"(x), "f"(y));
    return r;
}
__device__ __forceinline__ void unpack2(unsigned long long v, float &x, float &y) {
    asm("mov.b64 {%0, %1}, %2;" : "=f"(x), "=f"(y) : "l"(v));
}
__device__ __forceinline__ unsigned long long ffma2(unsigned long long a,
                                                    unsigned long long b,
                                                    unsigned long long c) {
    unsigned long long d;
    asm("fma.rn.f32x2 %0, %1, %2, %3;" : "=l"(d) : "l"(a), "l"(b), "l"(c));
    return d;
}

// E0 fp32 row: users in g_E4, items straight from input
__device__ __forceinline__ const float2 *e0row(int c, const float2 *__restrict__ item2) {
    return (c < NUSER) ? ((const float2 *)g_E4) + (size_t)c * 32
                       : item2 + (size_t)(c - NUSER) * 32;
}

// ================= launch 1: user copy + item fp16 convert + zero aux =============
#define COPYU_BLKS 3125            // NUSER*16/256
#define ITEM_BLKS  6250            // NITEM*16/256
#define ZERO_BLKS  586
#define INIT_BLKS (COPYU_BLKS + ITEM_BLKS + ZERO_BLKS)
__global__ void k_init(const float4 *__restrict__ ue, const float4 *__restrict__ ie) {
    int bid = blockIdx.x, tid = threadIdx.x;
    if (bid < COPYU_BLKS) {                       // user rows: fp32 copy + fp16
        int i = bid * 256 + tid;                  // i < NUSER*16 exactly
        float4 v = ue[i];
        g_E4[i] = v;
        g_Eh[2 * i]     = __floats2half2_rn(v.x, v.y);
        g_Eh[2 * i + 1] = __floats2half2_rn(v.z, v.w);
        return;
    }
    bid -= COPYU_BLKS;
    if (bid < ITEM_BLKS) {                        // item rows: fp16 only
        int i = bid * 256 + tid;                  // i < NITEM*16 exactly
        float4 v = ie[i];
        int o = NUSER * 16 + i;
        g_Eh[2 * o]     = __floats2half2_rn(v.x, v.y);
        g_Eh[2 * o + 1] = __floats2half2_rn(v.z, v.w);
        return;
    }
    bid -= ITEM_BLKS;
    int i = bid * 256 + tid;
    if (i < NNODE) { g_cnt[i] = 0; g_flag3[i] = 0; g_flag2[i] = 0; }
    if (i < NTILES) g_tflag[i] = 0;
    if (i == 0) g_n2 = 0;
}

// ================= launch 2: MLP+update (last wins) + slots/flags =================
__global__ void k_prep(const int *__restrict__ uidx, const float *__restrict__ uemb,
                       const float *__restrict__ ratio,
                       const int *__restrict__ pi, const int *__restrict__ ni,
                       const float *__restrict__ l1w, const float *__restrict__ l1b,
                       const float *__restrict__ l2w, const float *__restrict__ l2b,
                       const float *__restrict__ feat) {
    int bid = blockIdx.x, tid = threadIdx.x;
    if (bid < 4) {
        int b = bid * 256 + tid;
        if (b >= BB) return;
        int u = uidx[b];
        for (int b2 = b + 1; b2 < BB; b2++)
            if (uidx[b2] == u) return;            // later duplicate wins
        float f0 = feat[b * 4 + 0], f1 = feat[b * 4 + 1];
        float f2 = feat[b * 4 + 2], f3 = feat[b * 4 + 3];
        float h[32];
#pragma unroll
        for (int j = 0; j < 32; j++)
            h[j] = l1b[j] + f0 * l1w[j] + f1 * l1w[32 + j] + f2 * l1w[64 + j] + f3 * l1w[96 + j];
        float r = *ratio;
        float e[64];
#pragma unroll 4
        for (int o = 0; o < 64; o++) {
            float a = l2b[o];
#pragma unroll
            for (int j = 0; j < 32; j++) a += h[j] * l2w[j * 64 + o];
            e[o] = uemb[u * 64 + o] * (1.0f - r) + a * r;
        }
        float4 *er = g_E4 + (size_t)u * 16;
        __half2 *eh = g_Eh + (size_t)u * 32;
#pragma unroll
        for (int j = 0; j < 16; j++) {
            er[j] = make_float4(e[4 * j], e[4 * j + 1], e[4 * j + 2], e[4 * j + 3]);
            eh[2 * j]     = __floats2half2_rn(e[4 * j], e[4 * j + 1]);
            eh[2 * j + 1] = __floats2half2_rn(e[4 * j + 2], e[4 * j + 3]);
        }
        return;
    }
    int s = (bid - 4) * 256 + tid;
    if (s >= NSLOT) return;
    int node;
    if (s < 1024)       node = uidx[s];
    else if (s < 2048)  node = NUSER + pi[s - 1024];
    else                node = NUSER + ni[s - 2048];
    g_slot[s] = node;
    g_flag3[node] = 1;
    g_flag2[node] = 1;
}

// ---------------- shared gather body (fp32 sources) --------------------------------
__device__ __forceinline__ void gather_body(int t, float *__restrict__ out, int col_off,
                                            int do_norm, const float2 *__restrict__ item2,
                                            int src0) {
    int slot = t >> 5, lane = t & 31;
    if (slot >= NSLOT) return;
    int node = g_slot[slot];
    const float2 *rowp = src0 ? e0row(node, item2)
                              : ((const float2 *)g_E4) + (size_t)node * 32;
    float2 v = rowp[lane];
    if (do_norm) {
        float s = v.x * v.x + v.y * v.y;
#pragma unroll
        for (int o = 16; o > 0; o >>= 1) s += __shfl_xor_sync(0xffffffffu, s, o);
        float sc = 1.0f / fmaxf(sqrtf(s), 1e-12f);
        v.x *= sc; v.y *= sc;
    }
    ((float2 *)(out + (size_t)slot * 256 + col_off))[lane] = v;
}

// ================= launch 3: histogram + flag2 propagate + gather0 ================
#define NNZ_BLKS 9375
__global__ void k_nnzpass(const int *__restrict__ row, const int *__restrict__ col,
                          float *__restrict__ out, const float2 *__restrict__ item2) {
    int bid = blockIdx.x, tid = threadIdx.x;
    if (bid < NNZ_BLKS) {
        int i = bid * 256 + tid;
        if (i >= NNZV) return;
        int r = __ldg(row + i);
        atomicAdd(&g_cnt[r], 1);
        if (g_flag3[r]) g_flag2[__ldg(col + i)] = 1;
        return;
    }
    gather_body((bid - NNZ_BLKS) * 256 + tid, out, 0, 0, item2, 1);
}

// ================= launch 4: single-pass scan (decoupled lookback) ================
// 147 blocks <= 148 SMs: all co-resident, spin is safe. Also builds list2.
__global__ void k_scan() {
    __shared__ int wsum[8], rs[8], sS;
    int tid = threadIdx.x, lane = tid & 31, wid = tid >> 5, blk = blockIdx.x;
    int idx = blk * SCAN_TILE + tid * 4;
    int v0 = (idx + 0 < NNODE) ? g_cnt[idx + 0] : 0;
    int v1 = (idx + 1 < NNODE) ? g_cnt[idx + 1] : 0;
    int v2 = (idx + 2 < NNODE) ? g_cnt[idx + 2] : 0;
    int v3 = (idx + 3 < NNODE) ? g_cnt[idx + 3] : 0;
    int s = v0 + v1 + v2 + v3;
    int x = s;
#pragma unroll
    for (int o = 1; o < 32; o <<= 1) {
        int y = __shfl_up_sync(0xffffffffu, x, o);
        if (lane >= o) x += y;
    }
    if (lane == 31) wsum[wid] = x;
    __syncthreads();
    if (wid == 0) {
        int y = (lane < 8) ? wsum[lane] : 0;
#pragma unroll
        for (int o = 1; o < 8; o <<= 1) {
            int z = __shfl_up_sync(0xffffffffu, y, o);
            if (lane >= o) y += z;
        }
        if (lane < 8) wsum[lane] = y;
    }
    __syncthreads();
    int run = x - s + (wid > 0 ? wsum[wid - 1] : 0);   // exclusive in-tile prefix
    // publish this tile's total (encoded total+1 so 0 means "not ready")
    if (tid == 0) atomicExch(&g_tflag[blk], wsum[7] + 1);
    // lookback: thread tid polls predecessor tile tid
    int v = 0;
    if (tid < blk) {
        int t;
        while ((t = atomicAdd(&g_tflag[tid], 0)) == 0) {}
        v = t - 1;
    }
#pragma unroll
    for (int o = 16; o > 0; o >>= 1) v += __shfl_xor_sync(0xffffffffu, v, o);
    if (lane == 0) rs[wid] = v;
    __syncthreads();
    if (tid == 0) {
        int S = 0;
#pragma unroll
        for (int i = 0; i < 8; i++) S += rs[i];
        sS = S;
    }
    __syncthreads();
    int S = sS;
    int r0 = run + S, r1 = r0 + v0, r2 = r1 + v1, r3 = r2 + v2;
    if (idx + 0 < NNODE) { g_rp[idx + 0] = r0; g_pos[idx + 0] = r0;
        if (g_flag2[idx + 0]) g_list2[atomicAdd(&g_n2, 1)] = idx + 0; }
    if (idx + 1 < NNODE) { g_rp[idx + 1] = r1; g_pos[idx + 1] = r1;
        if (g_flag2[idx + 1]) g_list2[atomicAdd(&g_n2, 1)] = idx + 1; }
    if (idx + 2 < NNODE) { g_rp[idx + 2] = r2; g_pos[idx + 2] = r2;
        if (g_flag2[idx + 2]) g_list2[atomicAdd(&g_n2, 1)] = idx + 2; }
    if (idx + 3 < NNODE) { g_rp[idx + 3] = r3; g_pos[idx + 3] = r3;
        if (g_flag2[idx + 3]) g_list2[atomicAdd(&g_n2, 1)] = idx + 3; }
    if (blk == 0 && tid == 0) g_rp[NNODE] = NNZV;
}

// ================= launch 5: scatter (col,val) row-sorted =========================
__global__ void k_scatter(const int *__restrict__ row, const int *__restrict__ col,
                          const float *__restrict__ val) {
    int i = blockIdx.x * blockDim.x + threadIdx.x;
    if (i >= NNZV) return;
    int p = atomicAdd(&g_pos[row[i]], 1);
    g_cv[p] = make_int2(col[i], __float_as_int(val[i]));
}

// ================= CSR SpMM row body: fp16 gather, fp32 accumulate ================
__device__ __forceinline__ void spmm_row(int r, int lane) {
    int j = __ldg(&g_rp[r]), end = __ldg(&g_rp[r + 1]);
    float ax = 0.f, ay = 0.f;
#define LDE(c) __half22float2(__ldg(g_Eh + (size_t)(c) * 32 + lane))
    if ((j & 1) && j < end) {
        int2 c = __ldg(g_cv + j);
        float2 e = LDE(c.x);
        float v = __int_as_float(c.y);
        ax += v * e.x; ay += v * e.y;
        j++;
    }
    for (; j + 8 <= end; j += 8) {
        int4 q0 = __ldg((const int4 *)(g_cv + j));
        int4 q1 = __ldg((const int4 *)(g_cv + j + 2));
        int4 q2 = __ldg((const int4 *)(g_cv + j + 4));
        int4 q3 = __ldg((const int4 *)(g_cv + j + 6));
        float2 e0 = LDE(q0.x), e1 = LDE(q0.z);
        float2 e2 = LDE(q1.x), e3 = LDE(q1.z);
        float2 e4 = LDE(q2.x), e5 = LDE(q2.z);
        float2 e6 = LDE(q3.x), e7 = LDE(q3.z);
        ax += __int_as_float(q0.y) * e0.x; ay += __int_as_float(q0.y) * e0.y;
        ax += __int_as_float(q0.w) * e1.x; ay += __int_as_float(q0.w) * e1.y;
        ax += __int_as_float(q1.y) * e2.x; ay += __int_as_float(q1.y) * e2.y;
        ax += __int_as_float(q1.w) * e3.x; ay += __int_as_float(q1.w) * e3.y;
        ax += __int_as_float(q2.y) * e4.x; ay += __int_as_float(q2.y) * e4.y;
        ax += __int_as_float(q2.w) * e5.x; ay += __int_as_float(q2.w) * e5.y;
        ax += __int_as_float(q3.y) * e6.x; ay += __int_as_float(q3.y) * e6.y;
        ax += __int_as_float(q3.w) * e7.x; ay += __int_as_float(q3.w) * e7.y;
    }
    for (; j < end; j++) {
        int2 c = __ldg(g_cv + j);
        float2 e = LDE(c.x);
        float v = __int_as_float(c.y);
        ax += v * e.x; ay += v * e.y;
    }
#undef LDE
    ((float2 *)g_LE4)[(size_t)r * 32 + lane] = make_float2(ax, ay);
}

// MODE 0 = all rows (flat), 1 = list2 rows (grid-strided), 2 = slot rows (flat)
template <int MODE>
__global__ void k_spmm(int spmm_blks, float *__restrict__ out, int col_off,
                       const float2 *__restrict__ item2) {
    int bid = blockIdx.x;
    if (MODE != 0 && bid >= spmm_blks) {
        gather_body((bid - spmm_blks) * 256 + threadIdx.x, out, col_off, 1, item2, 0);
        return;
    }
    int lane = threadIdx.x & 31;
    int w = (bid * blockDim.x + threadIdx.x) >> 5;
    if (MODE == 0) {
        if (w < NNODE) spmm_row(w, lane);
    } else if (MODE == 1) {
        int n2 = g_n2;
        for (; w < n2; w += SP2_WARPS) spmm_row(g_list2[w], lane);
    } else {
        if (w < NSLOT) spmm_row(g_slot[w], lane);
    }
}

// ================= GEMM + leaky_relu, E in place, fp16 mirror epilogue ============
// MODE 0 = all rows (layer 1, E0 via select), 1 = list2 rows grid-strided (layer 2)
template <int MODE>
__global__ __launch_bounds__(128) void k_gemm(const float *__restrict__ w1,
                                              const float *__restrict__ b1,
                                              const float *__restrict__ w2,
                                              const float *__restrict__ b2,
                                              const float2 *__restrict__ item2) {
    __shared__ unsigned long long sW1[2048], sW2[2048], sB[32];
    const unsigned long long *w1p = (const unsigned long long *)w1;
    const unsigned long long *w2p = (const unsigned long long *)w2;
    for (int i = threadIdx.x; i < 2048; i += 128) { sW1[i] = w1p[i]; sW2[i] = w2p[i]; }
    if (threadIdx.x < 32) {
        int t = threadIdx.x;
        sB[t] = pack2(b1[2 * t] + b2[2 * t], b1[2 * t + 1] + b2[2 * t + 1]);
    }
    __syncthreads();

    int idx = blockIdx.x * 128 + threadIdx.x;
    int nrows = (MODE == 0) ? NNODE : g_n2;
    int stride = gridDim.x * 128;

    for (; idx < nrows; idx += stride) {
        int rrow = (MODE == 0) ? idx : g_list2[idx];

        unsigned long long acc[32];
#pragma unroll
        for (int j = 0; j < 32; j++) acc[j] = sB[j];

        const float4 *lep4 = (const float4 *)(g_LE4 + (size_t)rrow * 16);
        const float4 *ep4  = (MODE == 0) ? (const float4 *)e0row(rrow, item2)
                                         : (const float4 *)(g_E4 + (size_t)rrow * 16);

#pragma unroll
        for (int ph = 0; ph < 4; ph++) {
            float le[16], ee[16];
#pragma unroll
            for (int q = 0; q < 4; q++) {
                float4 a = __ldg(lep4 + ph * 4 + q);
                float4 b = __ldg(ep4 + ph * 4 + q);
                le[4 * q] = a.x; le[4 * q + 1] = a.y; le[4 * q + 2] = a.z; le[4 * q + 3] = a.w;
                ee[4 * q] = b.x; ee[4 * q + 1] = b.y; ee[4 * q + 2] = b.z; ee[4 * q + 3] = b.w;
            }
#pragma unroll
            for (int kk = 0; kk < 16; kk++) {
                int k = ph * 16 + kk;
                float a = le[kk] + ee[kk], m = le[kk] * ee[kk];
                unsigned long long a2 = pack2(a, a), m2 = pack2(m, m);
                const ulonglong2 *wA = (const ulonglong2 *)(sW1 + k * 32);
                const ulonglong2 *wB = (const ulonglong2 *)(sW2 + k * 32);
#pragma unroll
                for (int j = 0; j < 16; j++) {
                    ulonglong2 pa = wA[j];
                    ulonglong2 pb = wB[j];
                    acc[2 * j]     = ffma2(a2, pa.x, acc[2 * j]);
                    acc[2 * j + 1] = ffma2(a2, pa.y, acc[2 * j + 1]);
                    acc[2 * j]     = ffma2(m2, pb.x, acc[2 * j]);
                    acc[2 * j + 1] = ffma2(m2, pb.y, acc[2 * j + 1]);
                }
            }
        }

        float4 *o = g_E4 + (size_t)rrow * 16;
        __half2 *oh = g_Eh + (size_t)rrow * 32;
#pragma unroll
        for (int j = 0; j < 16; j++) {
            float x0, x1, x2, x3;
            unpack2(acc[2 * j], x0, x1);
            unpack2(acc[2 * j + 1], x2, x3);
            x0 = (x0 >= 0.f) ? x0 : 0.2f * x0;
            x1 = (x1 >= 0.f) ? x1 : 0.2f * x1;
            x2 = (x2 >= 0.f) ? x2 : 0.2f * x2;
            x3 = (x3 >= 0.f) ? x3 : 0.2f * x3;
            o[j] = make_float4(x0, x1, x2, x3);
            oh[2 * j]     = __floats2half2_rn(x0, x1);
            oh[2 * j + 1] = __floats2half2_rn(x2, x3);
        }
    }
}

// ================= final layer: GEMM + leaky + norm for slot rows =================
__global__ __launch_bounds__(128) void k_layer3(const float *__restrict__ w1,
                                                const float *__restrict__ b1,
                                                const float *__restrict__ w2,
                                                const float *__restrict__ b2,
                                                float *__restrict__ out) {
    __shared__ unsigned long long sW1[2048], sW2[2048], sB[32];
    const unsigned long long *w1p = (const unsigned long long *)w1;
    const unsigned long long *w2p = (const unsigned long long *)w2;
    for (int i = threadIdx.x; i < 2048; i += 128) { sW1[i] = w1p[i]; sW2[i] = w2p[i]; }
    if (threadIdx.x < 32) {
        int t = threadIdx.x;
        sB[t] = pack2(b1[2 * t] + b2[2 * t], b1[2 * t + 1] + b2[2 * t + 1]);
    }
    __syncthreads();

    int s = blockIdx.x * 128 + threadIdx.x;
    if (s >= NSLOT) return;
    int rrow = g_slot[s];

    unsigned long long acc[32];
#pragma unroll
    for (int j = 0; j < 32; j++) acc[j] = sB[j];

    const float4 *lep4 = (const float4 *)(g_LE4 + (size_t)rrow * 16);
    const float4 *ep4  = (const float4 *)(g_E4 + (size_t)rrow * 16);

#pragma unroll
    for (int ph = 0; ph < 4; ph++) {
        float le[16], ee[16];
#pragma unroll
        for (int q = 0; q < 4; q++) {
            float4 a = __ldg(lep4 + ph * 4 + q);
            float4 b = __ldg(ep4 + ph * 4 + q);
            le[4 * q] = a.x; le[4 * q + 1] = a.y; le[4 * q + 2] = a.z; le[4 * q + 3] = a.w;
            ee[4 * q] = b.x; ee[4 * q + 1] = b.y; ee[4 * q + 2] = b.z; ee[4 * q + 3] = b.w;
        }
#pragma unroll
        for (int kk = 0; kk < 16; kk++) {
            int k = ph * 16 + kk;
            float a = le[kk] + ee[kk], m = le[kk] * ee[kk];
            unsigned long long a2 = pack2(a, a), m2 = pack2(m, m);
            const ulonglong2 *wA = (const ulonglong2 *)(sW1 + k * 32);
            const ulonglong2 *wB = (const ulonglong2 *)(sW2 + k * 32);
#pragma unroll
            for (int j = 0; j < 16; j++) {
                ulonglong2 pa = wA[j];
                ulonglong2 pb = wB[j];
                acc[2 * j]     = ffma2(a2, pa.x, acc[2 * j]);
                acc[2 * j + 1] = ffma2(a2, pa.y, acc[2 * j + 1]);
                acc[2 * j]     = ffma2(m2, pb.x, acc[2 * j]);
                acc[2 * j + 1] = ffma2(m2, pb.y, acc[2 * j + 1]);
            }
        }
    }

    float ss = 0.f;
#pragma unroll
    for (int j = 0; j < 32; j++) {
        float x, y;
        unpack2(acc[j], x, y);
        x = (x >= 0.f) ? x : 0.2f * x;
        y = (y >= 0.f) ? y : 0.2f * y;
        acc[j] = pack2(x, y);
        ss += x * x + y * y;
    }
    float sc = 1.0f / fmaxf(sqrtf(ss), 1e-12f);
    float *op = out + (size_t)s * 256 + 192;
#pragma unroll
    for (int j = 0; j < 16; j++) {
        float x0, x1, x2, x3;
        unpack2(acc[2 * j], x0, x1);
        unpack2(acc[2 * j + 1], x2, x3);
        ((float4 *)op)[j] = make_float4(x0 * sc, x1 * sc, x2 * sc, x3 * sc);
    }
}

// =================================================================================
extern "C" void kernel_launch(void* const* d_in, const int* in_sizes, int n_in,
                              void* d_out, int out_size) {
    const float *user_emb, *item_emb, *user_feat, *lin1_w, *lin1_b, *lin2_w, *lin2_b;
    const float *w1, *b1, *w2, *b2, *lap_val, *mlp_ratio;
    const int *lap_row, *lap_col, *user_idx, *pos_idx, *neg_idx;

    if (in_sizes[2] == 4096) {
        user_emb  = (const float *)d_in[0];
        item_emb  = (const float *)d_in[1];
        user_feat = (const float *)d_in[2];
        lin1_w    = (const float *)d_in[3];
        lin1_b    = (const float *)d_in[4];
        lin2_w    = (const float *)d_in[5];
        lin2_b    = (const float *)d_in[6];
        w1        = (const float *)d_in[7];
        b1        = (const float *)d_in[8];
        w2        = (const float *)d_in[9];
        b2        = (const float *)d_in[10];
        lap_val   = (const float *)d_in[11];
        mlp_ratio = (const float *)d_in[12];
        lap_row   = (const int *)d_in[13];
        lap_col   = (const int *)d_in[14];
        user_idx  = (const int *)d_in[15];
        pos_idx   = (const int *)d_in[16];
        neg_idx   = (const int *)d_in[17];
    } else {
        user_emb  = (const float *)d_in[0];
        item_emb  = (const float *)d_in[1];
        lin1_w    = (const float *)d_in[2];
        lin1_b    = (const float *)d_in[3];
        lin2_w    = (const float *)d_in[4];
        lin2_b    = (const float *)d_in[5];
        w1        = (const float *)d_in[6];
        b1        = (const float *)d_in[7];
        w2        = (const float *)d_in[8];
        b2        = (const float *)d_in[9];
        lap_row   = (const int *)d_in[10];
        lap_col   = (const int *)d_in[11];
        lap_val   = (const float *)d_in[12];
        user_idx  = (const int *)d_in[13];
        user_feat = (const float *)d_in[14];
        pos_idx   = (const int *)d_in[15];
        neg_idx   = (const int *)d_in[16];
        mlp_ratio = (const float *)d_in[17];
    }

    float *out = (float *)d_out;
    const float2 *item2 = (const float2 *)item_emb;

    const int T = 256;
    const int gGath  = (NSLOT * 32 + T - 1) / T;    // 384
    const int gNnz   = (NNZV + T - 1) / T;          // 9375
    const int gSpmmF = (NNODE * 32 + T - 1) / T;    // 18750
    const int gSp2   = SP2_WARPS / 8;               // 4736
    const int gSp3   = (NSLOT * 32) / T;            // 384
    const int gGemm  = (NNODE + 127) / 128;         // 1172
    const int gL3    = (NSLOT + 127) / 128;         // 24

    // 1: user E0 copy(+fp16) + item fp16 convert + zero aux
    k_init<<<INIT_BLKS, T>>>((const float4 *)user_emb, (const float4 *)item_emb);
    // 2: fused MLP+scatter-update(+fp16) + slots/flags
    k_prep<<<16, T>>>(user_idx, user_emb, mlp_ratio, pos_idx, neg_idx,
                      lin1_w, lin1_b, lin2_w, lin2_b, user_feat);
    // 3: row histogram + flag2 propagate + gather E0 -> out[:,0:64]
    k_nnzpass<<<NNZ_BLKS + gGath, T>>>(lap_row, lap_col, out, item2);
    // 4: single-pass scan + list2 build
    k_scan<<<NTILES, T>>>();
    // 5: CSR scatter
    k_scatter<<<gNnz, T>>>(lap_row, lap_col, lap_val);

    // 6: layer-1 SpMM (full, fp16 gather)
    k_spmm<0><<<gSpmmF, T>>>(gSpmmF, nullptr, 0, item2);
    // 7: layer-1 GEMM (full) + fp16 epilogue
    k_gemm<0><<<gGemm, 128>>>(w1, b1, w2, b2, item2);
    // 8: layer-2 SpMM (list2, strided) || gather E1 -> out[:,64:128]
    k_spmm<1><<<gSp2 + gGath, T>>>(gSp2, out, 64, item2);
    // 9: layer-2 GEMM (list2, strided) + fp16 epilogue
    k_gemm<1><<<400, 128>>>(w1 + 4096, b1 + 64, w2 + 4096, b2 + 64, item2);
    // 10: layer-3 SpMM (slots) || gather E2 -> out[:,128:192]
    k_spmm<2><<<gSp3 + gGath, T>>>(gSp3, out, 128, item2);
    // 11: layer-3 GEMM + leaky + norm -> out[:,192:256]
    k_layer3<<<gL3, 128>>>(w1 + 2 * 4096, b1 + 2 * 64, w2 + 2 * 4096, b2 + 2 * 64, out);
}